// round 12
// baseline (speedup 1.0000x reference)
#include <cuda_runtime.h>
#include <cuda_fp16.h>
#include <cstdint>

#define B_ 32
#define C_ 64
#define H_ 128
#define W_ 128
#define HW_ (H_*W_)
#define NTOT_ (B_*C_*HW_)

#define GRP 4                 // batches per group (L2-resident qkv window)
#define NGRP (B_/GRP)

// fp16 scratch: q/k/v projections + fp16 copy of x for the residual read
__device__ __half g_q[NTOT_];
__device__ __half g_k[NTOT_];
__device__ __half g_v[NTOT_];
__device__ __half g_xh[NTOT_];

// ---------------- helpers ----------------
__device__ __forceinline__ uint32_t smem_u32(const void* p) {
    uint32_t a;
    asm("{ .reg .u64 t; cvta.to.shared.u64 t, %1; cvt.u32.u64 %0, t; }" : "=r"(a) : "l"(p));
    return a;
}
__device__ __forceinline__ uint32_t packh2(float lo, float hi) {
    __half2 h = __floats2half2_rn(lo, hi);
    return *reinterpret_cast<uint32_t*>(&h);
}
__device__ __forceinline__ void ldmx4(uint32_t* r, uint32_t addr) {
    asm volatile("ldmatrix.sync.aligned.m8n8.x4.shared.b16 {%0,%1,%2,%3}, [%4];"
        : "=r"(r[0]), "=r"(r[1]), "=r"(r[2]), "=r"(r[3]) : "r"(addr));
}
__device__ __forceinline__ void ldmx4t(uint32_t* r, uint32_t addr) {
    asm volatile("ldmatrix.sync.aligned.m8n8.x4.trans.shared.b16 {%0,%1,%2,%3}, [%4];"
        : "=r"(r[0]), "=r"(r[1]), "=r"(r[2]), "=r"(r[3]) : "r"(addr));
}
__device__ __forceinline__ void mma_f16(float* d, const uint32_t* a, const uint32_t* b) {
    asm volatile("mma.sync.aligned.m16n8k16.row.col.f32.f16.f16.f32 "
        "{%0,%1,%2,%3}, {%4,%5,%6,%7}, {%8,%9}, {%0,%1,%2,%3};"
        : "+f"(d[0]), "+f"(d[1]), "+f"(d[2]), "+f"(d[3])
        : "r"(a[0]), "r"(a[1]), "r"(a[2]), "r"(a[3]), "r"(b[0]), "r"(b[1]));
}
#define CP16(dst, src) asm volatile("cp.async.cg.shared.global [%0], [%1], 16;" :: "r"(dst), "l"(src) : "memory")
#define CP_COMMIT()    asm volatile("cp.async.commit_group;" ::: "memory")
#define CP_WAIT(n)     asm volatile("cp.async.wait_group %0;" :: "n"(n) : "memory")

#define XPH 136
#define WPH 72
#define PH  136
#define PROJ_SMEM (64*XPH*2 + 3*64*WPH*2)
#define ATTN_SMEM (2 * 128 * PH * 2)
#define CMB_SMEM  (ATTN_SMEM > PROJ_SMEM ? ATTN_SMEM : PROJ_SMEM)

// ---------------------------------------------------------------------------
// proj body: q/k/v = W @ x + b (fp16 HMMA), q pre-scaled; also stores fp16 x.
// __noinline__: isolates register allocation from the attn path (no union).
// ---------------------------------------------------------------------------
__device__ __noinline__ void proj_body(
    const float* __restrict__ x,
    const float* __restrict__ Wq, const float* __restrict__ bq,
    const float* __restrict__ Wk, const float* __restrict__ bk,
    const float* __restrict__ Wv, const float* __restrict__ bv,
    int b, int px0, __half* smp)
{
    __half* Xs = smp;
    __half* Ws = smp + 64 * XPH;
    const uint32_t smb = smem_u32(smp);
    const uint32_t XsB = smb, WsB = smb + 64 * XPH * 2;

    const int tid  = threadIdx.x;
    const int w    = tid >> 5;
    const int lane = tid & 31;
    const int g    = lane >> 2;
    const int tg   = lane & 3;
    const int m0   = (w & 3) * 16;
    const int n0   = (w >> 2) * 64;

    // Fill X tile (fp32 -> fp16) and write the fp16 x sidecar for attn
    const float* xb = x + (size_t)b * C_ * HW_ + px0;
    __half* xhb = g_xh + (size_t)b * C_ * HW_ + px0;
    #pragma unroll 4
    for (int e = tid; e < 2048; e += 256) {
        int r = e >> 5, c4 = e & 31;
        float4 v = *((const float4*)(xb + r * HW_) + c4);
        uint2 hv = make_uint2(packh2(v.x, v.y), packh2(v.z, v.w));
        *(uint2*)(Xs + r * XPH + c4 * 4) = hv;
        *(uint2*)(xhb + r * HW_ + c4 * 4) = hv;
    }
    #pragma unroll 4
    for (int e = tid; e < 3 * 2048; e += 256) {
        int mtx = e >> 11, i = e & 2047;
        int o = i >> 5, c2 = i & 31;
        const float* Wm = (mtx == 0) ? Wq : (mtx == 1) ? Wk : Wv;
        float2 wv = *((const float2*)(Wm + o * 64) + c2);
        *(uint32_t*)(Ws + mtx * 64 * WPH + o * WPH + c2 * 2) = packh2(wv.x, wv.y);
    }
    __syncthreads();

    const int rsel = lane & 15;
    const int csel = (lane & 16) >> 1;

    #pragma unroll
    for (int mtx = 0; mtx < 3; mtx++) {
        const uint32_t WtB = WsB + (uint32_t)mtx * 64 * WPH * 2;
        float acc[8][4];
        #pragma unroll
        for (int nt = 0; nt < 8; nt++)
            #pragma unroll
            for (int j = 0; j < 4; j++) acc[nt][j] = 0.f;

        #pragma unroll
        for (int k0 = 0; k0 < 64; k0 += 16) {
            uint32_t a[4];
            ldmx4(a, WtB + (uint32_t)((m0 + rsel) * WPH + k0 + csel) * 2);
            #pragma unroll
            for (int ntp = 0; ntp < 4; ntp++) {
                uint32_t bb[4];
                ldmx4t(bb, XsB + (uint32_t)((k0 + rsel) * XPH + n0 + ntp * 16 + csel) * 2);
                mma_f16(acc[2 * ntp],     a, bb);
                mma_f16(acc[2 * ntp + 1], a, bb + 2);
            }
        }

        const float* bm = (mtx == 0) ? bq : (mtx == 1) ? bk : bv;
        __half* gout = ((mtx == 0) ? g_q : (mtx == 1) ? g_k : g_v);
        const float sc = (mtx == 0) ? 0.0078125f : 1.0f;   // 1/sqrt(HW) into q
        float bias0 = bm[m0 + g], bias1 = bm[m0 + g + 8];
        __half* orow0 = gout + ((size_t)b * C_ + m0 + g) * HW_ + px0;
        __half* orow1 = orow0 + 8 * HW_;
        #pragma unroll
        for (int nt = 0; nt < 8; nt++) {
            int col = n0 + nt * 8 + 2 * tg;
            *(uint32_t*)(orow0 + col) =
                packh2((acc[nt][0] + bias0) * sc, (acc[nt][1] + bias0) * sc);
            *(uint32_t*)(orow1 + col) =
                packh2((acc[nt][2] + bias1) * sc, (acc[nt][3] + bias1) * sc);
        }
    }
}

// ---------------------------------------------------------------------------
// attn body: per-(b,c) slice, fp16 HMMA, register P, fp16 residual sidecar.
// __noinline__: register-allocated independently (126 regs, zero spill).
// ---------------------------------------------------------------------------
__device__ __noinline__ void attn_body(
    float* __restrict__ out, int bc, __half* sma)
{
    const uint32_t smb = smem_u32(sma);
    const uint32_t KsB = smb, VsB = smb + 128 * PH * 2;

    const size_t base = (size_t)bc * HW_;
    const int tid  = threadIdx.x;
    const int wid  = tid >> 5;
    const int lane = tid & 31;
    const int g    = lane >> 2;
    const int tg   = lane & 3;
    const int m0   = wid * 16;
    const int rsel = lane & 15;
    const int csel = (lane & 16) >> 1;

    // Async fills: K -> group0, V -> group1
    const uint4* kg = (const uint4*)(g_k + base);
    const uint4* vg = (const uint4*)(g_v + base);
    #pragma unroll
    for (int e = tid; e < 2048; e += 256) {
        uint32_t off = (uint32_t)((e >> 4) * PH + (e & 15) * 8) * 2;
        CP16(KsB + off, kg + e);
    }
    CP_COMMIT();
    #pragma unroll
    for (int e = tid; e < 2048; e += 256) {
        uint32_t off = (uint32_t)((e >> 4) * PH + (e & 15) * 8) * 2;
        CP16(VsB + off, vg + e);
    }
    CP_COMMIT();

    // Q A-fragments straight from gmem (overlaps fills; L2-resident)
    const __half* qg = g_q + base;
    uint32_t aq[8][4];
    #pragma unroll
    for (int ks = 0; ks < 8; ks++) {
        const int k0 = ks * 16;
        aq[ks][0] = *(const uint32_t*)(qg + (m0 + g) * 128 + k0 + 2 * tg);
        aq[ks][1] = *(const uint32_t*)(qg + (m0 + g + 8) * 128 + k0 + 2 * tg);
        aq[ks][2] = *(const uint32_t*)(qg + (m0 + g) * 128 + k0 + 8 + 2 * tg);
        aq[ks][3] = *(const uint32_t*)(qg + (m0 + g + 8) * 128 + k0 + 8 + 2 * tg);
    }

    CP_WAIT(1);          // K landed
    __syncthreads();

    // ---- MM1: S = Q.K^T (q pre-scaled) ----
    float acc[16][4];
    #pragma unroll
    for (int nt = 0; nt < 16; nt++)
        #pragma unroll
        for (int j = 0; j < 4; j++) acc[nt][j] = 0.f;

    #pragma unroll
    for (int ks = 0; ks < 8; ks++) {
        const int k0 = ks * 16;
        #pragma unroll
        for (int ntp = 0; ntp < 8; ntp++) {
            uint32_t kb[4];
            ldmx4(kb, KsB + (uint32_t)((ntp * 16 + csel + (lane & 7)) * PH + k0 + (lane & 8)) * 2);
            mma_f16(acc[2 * ntp],     aq[ks], kb);
            mma_f16(acc[2 * ntp + 1], aq[ks], kb + 2);
        }
    }

    // ---- softmax; P packed to fp16 in regs ----
    float sum0 = 0.f, sum1 = 0.f;
    uint32_t ph[16][2];
    #pragma unroll
    for (int nt = 0; nt < 16; nt++) {
        float e0 = __expf(acc[nt][0]);
        float e1 = __expf(acc[nt][1]);
        float e2 = __expf(acc[nt][2]);
        float e3 = __expf(acc[nt][3]);
        sum0 += e0 + e1;  sum1 += e2 + e3;
        ph[nt][0] = packh2(e0, e1);
        ph[nt][1] = packh2(e2, e3);
    }
    sum0 += __shfl_xor_sync(0xffffffffu, sum0, 1);
    sum0 += __shfl_xor_sync(0xffffffffu, sum0, 2);
    sum1 += __shfl_xor_sync(0xffffffffu, sum1, 1);
    sum1 += __shfl_xor_sync(0xffffffffu, sum1, 2);
    const float rin0 = 1.0f / sum0, rin1 = 1.0f / sum1;

    CP_WAIT(0);          // V landed
    __syncthreads();

    // ---- MM2: O = P.V + x (fp16 sidecar residual) ----
    const __half* xh = g_xh + base;
    float* og = out + base;
    #pragma unroll
    for (int hf = 0; hf < 2; hf++) {
        const int w00 = hf * 64;

        // Prefetch fp16 residuals for this half (hidden under mma chain)
        __half2 xv[16];
        #pragma unroll
        for (int wt = 0; wt < 8; wt++) {
            int col = w00 + wt * 8 + 2 * tg;
            xv[2 * wt]     = *(const __half2*)(xh + (m0 + g) * W_ + col);
            xv[2 * wt + 1] = *(const __half2*)(xh + (m0 + g + 8) * W_ + col);
        }

        float o[8][4];
        #pragma unroll
        for (int wt = 0; wt < 8; wt++)
            #pragma unroll
            for (int j = 0; j < 4; j++) o[wt][j] = 0.f;

        #pragma unroll
        for (int s = 0; s < 8; s++) {
            const int k0 = s * 16;
            uint32_t a[4] = { ph[2*s][0], ph[2*s][1], ph[2*s+1][0], ph[2*s+1][1] };
            #pragma unroll
            for (int wtp = 0; wtp < 4; wtp++) {
                uint32_t vb[4];
                ldmx4t(vb, VsB + (uint32_t)((k0 + rsel) * PH + w00 + wtp * 16 + csel) * 2);
                mma_f16(o[2 * wtp],     a, vb);
                mma_f16(o[2 * wtp + 1], a, vb + 2);
            }
        }

        #pragma unroll
        for (int wt = 0; wt < 8; wt++) {
            int col = w00 + wt * 8 + 2 * tg;
            float2 f0 = __half22float2(xv[2 * wt]);
            float2 f1 = __half22float2(xv[2 * wt + 1]);
            *(float2*)(og + (m0 + g) * W_ + col) =
                make_float2(o[wt][0] * rin0 + f0.x, o[wt][1] * rin0 + f0.y);
            *(float2*)(og + (m0 + g + 8) * W_ + col) =
                make_float2(o[wt][2] * rin1 + f1.x, o[wt][3] * rin1 + f1.y);
        }
    }
}

// ---------------------------------------------------------------------------
// Combo kernel: first n_attn CTAs run attn(group L-1), rest run proj(group L).
// Bodies are __noinline__ so each path keeps its own register budget
// (attn 126 / proj ~85) instead of the inlined union (174 -> spills at 128).
// ---------------------------------------------------------------------------
__global__ __launch_bounds__(256, 2) void combo_kernel(
    const float* __restrict__ x,
    const float* __restrict__ Wq, const float* __restrict__ bq,
    const float* __restrict__ Wk, const float* __restrict__ bk,
    const float* __restrict__ Wv, const float* __restrict__ bv,
    float* __restrict__ out,
    int proj_b0, int attn_bc0, int n_attn)
{
    extern __shared__ __half smc[];
    const int bi = (int)blockIdx.x;
    if (bi < n_attn) {
        attn_body(out, attn_bc0 + bi, smc);
    } else {
        const int pb = bi - n_attn;
        proj_body(x, Wq, bq, Wk, bk, Wv, bv,
                  proj_b0 + (pb >> 7), (pb & 127) * 128, smc);
    }
}

// ---------------------------------------------------------------------------
extern "C" void kernel_launch(void* const* d_in, const int* in_sizes, int n_in,
                              void* d_out, int out_size)
{
    const float* x  = (const float*)d_in[0];
    const float* Wq = (const float*)d_in[1];
    const float* bq = (const float*)d_in[2];
    const float* Wk = (const float*)d_in[3];
    const float* bk = (const float*)d_in[4];
    const float* Wv = (const float*)d_in[5];
    const float* bv = (const float*)d_in[6];
    float* out = (float*)d_out;

    cudaFuncSetAttribute(combo_kernel, cudaFuncAttributeMaxDynamicSharedMemorySize, CMB_SMEM);

    // Pipelined: launch L = attn(group L-1) || proj(group L)
    for (int L = 0; L <= NGRP; L++) {
        int n_proj = (L < NGRP) ? 512 : 0;
        int n_attn = (L > 0) ? 256 : 0;
        combo_kernel<<<n_proj + n_attn, 256, CMB_SMEM>>>(
            x, Wq, bq, Wk, bk, Wv, bv, out,
            L * GRP, (L - 1) * GRP * 64, n_attn);
    }
}

// round 13
// speedup vs baseline: 1.1053x; 1.1053x over previous
#include <cuda_runtime.h>
#include <cuda_fp16.h>
#include <cstdint>

#define B_ 32
#define C_ 64
#define H_ 128
#define W_ 128
#define HW_ (H_*W_)
#define NTOT_ (B_*C_*HW_)

#define GRP 4                 // batches per group (L2-resident qkv window)
#define NGRP (B_/GRP)

// fp16 scratch: q/k/v projections + fp16 copy of x for the residual read
__device__ __half g_q[NTOT_];
__device__ __half g_k[NTOT_];
__device__ __half g_v[NTOT_];
__device__ __half g_xh[NTOT_];

// ---------------- helpers ----------------
__device__ __forceinline__ uint32_t smem_u32(const void* p) {
    uint32_t a;
    asm("{ .reg .u64 t; cvta.to.shared.u64 t, %1; cvt.u32.u64 %0, t; }" : "=r"(a) : "l"(p));
    return a;
}
__device__ __forceinline__ uint32_t packh2(float lo, float hi) {
    __half2 h = __floats2half2_rn(lo, hi);
    return *reinterpret_cast<uint32_t*>(&h);
}
__device__ __forceinline__ void ldmx4(uint32_t* r, uint32_t addr) {
    asm volatile("ldmatrix.sync.aligned.m8n8.x4.shared.b16 {%0,%1,%2,%3}, [%4];"
        : "=r"(r[0]), "=r"(r[1]), "=r"(r[2]), "=r"(r[3]) : "r"(addr));
}
__device__ __forceinline__ void ldmx4t(uint32_t* r, uint32_t addr) {
    asm volatile("ldmatrix.sync.aligned.m8n8.x4.trans.shared.b16 {%0,%1,%2,%3}, [%4];"
        : "=r"(r[0]), "=r"(r[1]), "=r"(r[2]), "=r"(r[3]) : "r"(addr));
}
__device__ __forceinline__ void mma_f16(float* d, const uint32_t* a, const uint32_t* b) {
    asm volatile("mma.sync.aligned.m16n8k16.row.col.f32.f16.f16.f32 "
        "{%0,%1,%2,%3}, {%4,%5,%6,%7}, {%8,%9}, {%0,%1,%2,%3};"
        : "+f"(d[0]), "+f"(d[1]), "+f"(d[2]), "+f"(d[3])
        : "r"(a[0]), "r"(a[1]), "r"(a[2]), "r"(a[3]), "r"(b[0]), "r"(b[1]));
}
#define CP16(dst, src) asm volatile("cp.async.cg.shared.global [%0], [%1], 16;" :: "r"(dst), "l"(src) : "memory")
#define CP_COMMIT()    asm volatile("cp.async.commit_group;" ::: "memory")
#define CP_WAIT(n)     asm volatile("cp.async.wait_group %0;" :: "n"(n) : "memory")
// Drop a dirty L2 line WITHOUT write-back (scratch is dead after attn reads it)
#define L2_DISCARD(p)  asm volatile("discard.global.L2 [%0], 128;" :: "l"(p) : "memory")

#define XPH 136
#define WPH 72
#define PH  136
#define PROJ_SMEM (64*XPH*2 + 3*64*WPH*2)
#define ATTN_SMEM (2 * 128 * PH * 2)
#define CMB_SMEM  (ATTN_SMEM > PROJ_SMEM ? ATTN_SMEM : PROJ_SMEM)

// ---------------------------------------------------------------------------
// proj body: q/k/v = W @ x + b (fp16 HMMA), q pre-scaled; also stores fp16 x.
// ---------------------------------------------------------------------------
__device__ __forceinline__ void proj_body(
    const float* __restrict__ x,
    const float* __restrict__ Wq, const float* __restrict__ bq,
    const float* __restrict__ Wk, const float* __restrict__ bk,
    const float* __restrict__ Wv, const float* __restrict__ bv,
    int b, int px0, __half* smp)
{
    __half* Xs = smp;
    __half* Ws = smp + 64 * XPH;
    const uint32_t smb = smem_u32(smp);
    const uint32_t XsB = smb, WsB = smb + 64 * XPH * 2;

    const int tid  = threadIdx.x;
    const int w    = tid >> 5;
    const int lane = tid & 31;
    const int g    = lane >> 2;
    const int tg   = lane & 3;
    const int m0   = (w & 3) * 16;
    const int n0   = (w >> 2) * 64;

    // Fill X tile (fp32 -> fp16) and write the fp16 x sidecar for attn
    const float* xb = x + (size_t)b * C_ * HW_ + px0;
    __half* xhb = g_xh + (size_t)b * C_ * HW_ + px0;
    #pragma unroll 4
    for (int e = tid; e < 2048; e += 256) {
        int r = e >> 5, c4 = e & 31;
        float4 v = *((const float4*)(xb + r * HW_) + c4);
        uint2 hv = make_uint2(packh2(v.x, v.y), packh2(v.z, v.w));
        *(uint2*)(Xs + r * XPH + c4 * 4) = hv;
        *(uint2*)(xhb + r * HW_ + c4 * 4) = hv;
    }
    #pragma unroll 4
    for (int e = tid; e < 3 * 2048; e += 256) {
        int mtx = e >> 11, i = e & 2047;
        int o = i >> 5, c2 = i & 31;
        const float* Wm = (mtx == 0) ? Wq : (mtx == 1) ? Wk : Wv;
        float2 wv = *((const float2*)(Wm + o * 64) + c2);
        *(uint32_t*)(Ws + mtx * 64 * WPH + o * WPH + c2 * 2) = packh2(wv.x, wv.y);
    }
    __syncthreads();

    const int rsel = lane & 15;
    const int csel = (lane & 16) >> 1;

    #pragma unroll
    for (int mtx = 0; mtx < 3; mtx++) {
        const uint32_t WtB = WsB + (uint32_t)mtx * 64 * WPH * 2;
        float acc[8][4];
        #pragma unroll
        for (int nt = 0; nt < 8; nt++)
            #pragma unroll
            for (int j = 0; j < 4; j++) acc[nt][j] = 0.f;

        #pragma unroll
        for (int k0 = 0; k0 < 64; k0 += 16) {
            uint32_t a[4];
            ldmx4(a, WtB + (uint32_t)((m0 + rsel) * WPH + k0 + csel) * 2);
            #pragma unroll
            for (int ntp = 0; ntp < 4; ntp++) {
                uint32_t bb[4];
                ldmx4t(bb, XsB + (uint32_t)((k0 + rsel) * XPH + n0 + ntp * 16 + csel) * 2);
                mma_f16(acc[2 * ntp],     a, bb);
                mma_f16(acc[2 * ntp + 1], a, bb + 2);
            }
        }

        const float* bm = (mtx == 0) ? bq : (mtx == 1) ? bk : bv;
        __half* gout = ((mtx == 0) ? g_q : (mtx == 1) ? g_k : g_v);
        const float sc = (mtx == 0) ? 0.0078125f : 1.0f;   // 1/sqrt(HW) into q
        float bias0 = bm[m0 + g], bias1 = bm[m0 + g + 8];
        __half* orow0 = gout + ((size_t)b * C_ + m0 + g) * HW_ + px0;
        __half* orow1 = orow0 + 8 * HW_;
        #pragma unroll
        for (int nt = 0; nt < 8; nt++) {
            int col = n0 + nt * 8 + 2 * tg;
            *(uint32_t*)(orow0 + col) =
                packh2((acc[nt][0] + bias0) * sc, (acc[nt][1] + bias0) * sc);
            *(uint32_t*)(orow1 + col) =
                packh2((acc[nt][2] + bias1) * sc, (acc[nt][3] + bias1) * sc);
        }
    }
}

// ---------------------------------------------------------------------------
// attn body: per-(b,c) slice, fp16 HMMA, register P, fp16 residual sidecar.
// Ends by L2-discarding its dead qkv/xh slices (no DRAM write-back).
// ---------------------------------------------------------------------------
__device__ __forceinline__ void attn_body(
    float* __restrict__ out, int bc, __half* sma)
{
    const uint32_t smb = smem_u32(sma);
    const uint32_t KsB = smb, VsB = smb + 128 * PH * 2;

    const size_t base = (size_t)bc * HW_;
    const int tid  = threadIdx.x;
    const int wid  = tid >> 5;
    const int lane = tid & 31;
    const int g    = lane >> 2;
    const int tg   = lane & 3;
    const int m0   = wid * 16;
    const int rsel = lane & 15;
    const int csel = (lane & 16) >> 1;

    // Async fills: K -> group0, V -> group1
    const uint4* kg = (const uint4*)(g_k + base);
    const uint4* vg = (const uint4*)(g_v + base);
    #pragma unroll
    for (int e = tid; e < 2048; e += 256) {
        uint32_t off = (uint32_t)((e >> 4) * PH + (e & 15) * 8) * 2;
        CP16(KsB + off, kg + e);
    }
    CP_COMMIT();
    #pragma unroll
    for (int e = tid; e < 2048; e += 256) {
        uint32_t off = (uint32_t)((e >> 4) * PH + (e & 15) * 8) * 2;
        CP16(VsB + off, vg + e);
    }
    CP_COMMIT();

    // Q A-fragments straight from gmem (overlaps fills; L2-resident)
    const __half* qg = g_q + base;
    uint32_t aq[8][4];
    #pragma unroll
    for (int ks = 0; ks < 8; ks++) {
        const int k0 = ks * 16;
        aq[ks][0] = *(const uint32_t*)(qg + (m0 + g) * 128 + k0 + 2 * tg);
        aq[ks][1] = *(const uint32_t*)(qg + (m0 + g + 8) * 128 + k0 + 2 * tg);
        aq[ks][2] = *(const uint32_t*)(qg + (m0 + g) * 128 + k0 + 8 + 2 * tg);
        aq[ks][3] = *(const uint32_t*)(qg + (m0 + g + 8) * 128 + k0 + 8 + 2 * tg);
    }

    CP_WAIT(1);          // K landed
    __syncthreads();

    // ---- MM1: S = Q.K^T (q pre-scaled) ----
    float acc[16][4];
    #pragma unroll
    for (int nt = 0; nt < 16; nt++)
        #pragma unroll
        for (int j = 0; j < 4; j++) acc[nt][j] = 0.f;

    #pragma unroll
    for (int ks = 0; ks < 8; ks++) {
        const int k0 = ks * 16;
        #pragma unroll
        for (int ntp = 0; ntp < 8; ntp++) {
            uint32_t kb[4];
            ldmx4(kb, KsB + (uint32_t)((ntp * 16 + csel + (lane & 7)) * PH + k0 + (lane & 8)) * 2);
            mma_f16(acc[2 * ntp],     aq[ks], kb);
            mma_f16(acc[2 * ntp + 1], aq[ks], kb + 2);
        }
    }

    // ---- softmax; P packed to fp16 in regs ----
    float sum0 = 0.f, sum1 = 0.f;
    uint32_t ph[16][2];
    #pragma unroll
    for (int nt = 0; nt < 16; nt++) {
        float e0 = __expf(acc[nt][0]);
        float e1 = __expf(acc[nt][1]);
        float e2 = __expf(acc[nt][2]);
        float e3 = __expf(acc[nt][3]);
        sum0 += e0 + e1;  sum1 += e2 + e3;
        ph[nt][0] = packh2(e0, e1);
        ph[nt][1] = packh2(e2, e3);
    }
    sum0 += __shfl_xor_sync(0xffffffffu, sum0, 1);
    sum0 += __shfl_xor_sync(0xffffffffu, sum0, 2);
    sum1 += __shfl_xor_sync(0xffffffffu, sum1, 1);
    sum1 += __shfl_xor_sync(0xffffffffu, sum1, 2);
    const float rin0 = 1.0f / sum0, rin1 = 1.0f / sum1;

    CP_WAIT(0);          // V landed
    __syncthreads();

    // ---- MM2: O = P.V + x (fp16 sidecar residual) ----
    const __half* xh = g_xh + base;
    float* og = out + base;
    #pragma unroll
    for (int hf = 0; hf < 2; hf++) {
        const int w00 = hf * 64;

        // Prefetch fp16 residuals for this half (hidden under mma chain)
        __half2 xv[16];
        #pragma unroll
        for (int wt = 0; wt < 8; wt++) {
            int col = w00 + wt * 8 + 2 * tg;
            xv[2 * wt]     = *(const __half2*)(xh + (m0 + g) * W_ + col);
            xv[2 * wt + 1] = *(const __half2*)(xh + (m0 + g + 8) * W_ + col);
        }

        float o[8][4];
        #pragma unroll
        for (int wt = 0; wt < 8; wt++)
            #pragma unroll
            for (int j = 0; j < 4; j++) o[wt][j] = 0.f;

        #pragma unroll
        for (int s = 0; s < 8; s++) {
            const int k0 = s * 16;
            uint32_t a[4] = { ph[2*s][0], ph[2*s][1], ph[2*s+1][0], ph[2*s+1][1] };
            #pragma unroll
            for (int wtp = 0; wtp < 4; wtp++) {
                uint32_t vb[4];
                ldmx4t(vb, VsB + (uint32_t)((k0 + rsel) * PH + w00 + wtp * 16 + csel) * 2);
                mma_f16(o[2 * wtp],     a, vb);
                mma_f16(o[2 * wtp + 1], a, vb + 2);
            }
        }

        #pragma unroll
        for (int wt = 0; wt < 8; wt++) {
            int col = w00 + wt * 8 + 2 * tg;
            float2 f0 = __half22float2(xv[2 * wt]);
            float2 f1 = __half22float2(xv[2 * wt + 1]);
            *(float2*)(og + (m0 + g) * W_ + col) =
                make_float2(o[wt][0] * rin0 + f0.x, o[wt][1] * rin0 + f0.y);
            *(float2*)(og + (m0 + g + 8) * W_ + col) =
                make_float2(o[wt][2] * rin1 + f1.x, o[wt][3] * rin1 + f1.y);
        }
    }

    // ---- discard dead scratch lines from L2 (skip the DRAM write-back) ----
    // This CTA is the unique reader of its (b,c) slices; after the barrier,
    // all loads from them are complete. Each slice = 32 KB = 256 x 128B lines.
    __syncthreads();
    {
        const char* pq = (const char*)(g_q  + base);
        const char* pk = (const char*)(g_k  + base);
        const char* pv = (const char*)(g_v  + base);
        const char* px = (const char*)(g_xh + base);
        const int i = tid;           // 256 threads -> one line each per array
        L2_DISCARD(pq + i * 128);
        L2_DISCARD(pk + i * 128);
        L2_DISCARD(pv + i * 128);
        L2_DISCARD(px + i * 128);
    }
}

// ---------------------------------------------------------------------------
// Combo kernel: first n_attn CTAs run attn(group L-1), rest run proj(group L).
// ---------------------------------------------------------------------------
__global__ __launch_bounds__(256, 2) void combo_kernel(
    const float* __restrict__ x,
    const float* __restrict__ Wq, const float* __restrict__ bq,
    const float* __restrict__ Wk, const float* __restrict__ bk,
    const float* __restrict__ Wv, const float* __restrict__ bv,
    float* __restrict__ out,
    int proj_b0, int attn_bc0, int n_attn)
{
    extern __shared__ __half smc[];
    const int bi = (int)blockIdx.x;
    if (bi < n_attn) {
        attn_body(out, attn_bc0 + bi, smc);
    } else {
        const int pb = bi - n_attn;
        proj_body(x, Wq, bq, Wk, bk, Wv, bv,
                  proj_b0 + (pb >> 7), (pb & 127) * 128, smc);
    }
}

// ---------------------------------------------------------------------------
extern "C" void kernel_launch(void* const* d_in, const int* in_sizes, int n_in,
                              void* d_out, int out_size)
{
    const float* x  = (const float*)d_in[0];
    const float* Wq = (const float*)d_in[1];
    const float* bq = (const float*)d_in[2];
    const float* Wk = (const float*)d_in[3];
    const float* bk = (const float*)d_in[4];
    const float* Wv = (const float*)d_in[5];
    const float* bv = (const float*)d_in[6];
    float* out = (float*)d_out;

    cudaFuncSetAttribute(combo_kernel, cudaFuncAttributeMaxDynamicSharedMemorySize, CMB_SMEM);

    // Pipelined: launch L = attn(group L-1) || proj(group L)
    for (int L = 0; L <= NGRP; L++) {
        int n_proj = (L < NGRP) ? 512 : 0;
        int n_attn = (L > 0) ? 256 : 0;
        combo_kernel<<<n_proj + n_attn, 256, CMB_SMEM>>>(
            x, Wq, bq, Wk, bk, Wv, bv, out,
            L * GRP, (L - 1) * GRP * 64, n_attn);
    }
}

// round 14
// speedup vs baseline: 1.1054x; 1.0001x over previous
#include <cuda_runtime.h>
#include <cuda_fp16.h>
#include <cstdint>

#define B_ 32
#define C_ 64
#define H_ 128
#define W_ 128
#define HW_ (H_*W_)
#define NTOT_ (B_*C_*HW_)

#define GRP 4                 // batches per group (L2-resident qkv window)
#define NGRP (B_/GRP)

// fp16 scratch: q/k/v projections + fp16 copy of x for the residual read
__device__ __half g_q[NTOT_];
__device__ __half g_k[NTOT_];
__device__ __half g_v[NTOT_];
__device__ __half g_xh[NTOT_];

// ---------------- helpers ----------------
__device__ __forceinline__ uint32_t smem_u32(const void* p) {
    uint32_t a;
    asm("{ .reg .u64 t; cvta.to.shared.u64 t, %1; cvt.u32.u64 %0, t; }" : "=r"(a) : "l"(p));
    return a;
}
__device__ __forceinline__ uint32_t packh2(float lo, float hi) {
    __half2 h = __floats2half2_rn(lo, hi);
    return *reinterpret_cast<uint32_t*>(&h);
}
__device__ __forceinline__ void ldmx4(uint32_t* r, uint32_t addr) {
    asm volatile("ldmatrix.sync.aligned.m8n8.x4.shared.b16 {%0,%1,%2,%3}, [%4];"
        : "=r"(r[0]), "=r"(r[1]), "=r"(r[2]), "=r"(r[3]) : "r"(addr));
}
__device__ __forceinline__ void ldmx4t(uint32_t* r, uint32_t addr) {
    asm volatile("ldmatrix.sync.aligned.m8n8.x4.trans.shared.b16 {%0,%1,%2,%3}, [%4];"
        : "=r"(r[0]), "=r"(r[1]), "=r"(r[2]), "=r"(r[3]) : "r"(addr));
}
__device__ __forceinline__ void mma_f16(float* d, const uint32_t* a, const uint32_t* b) {
    asm volatile("mma.sync.aligned.m16n8k16.row.col.f32.f16.f16.f32 "
        "{%0,%1,%2,%3}, {%4,%5,%6,%7}, {%8,%9}, {%0,%1,%2,%3};"
        : "+f"(d[0]), "+f"(d[1]), "+f"(d[2]), "+f"(d[3])
        : "r"(a[0]), "r"(a[1]), "r"(a[2]), "r"(a[3]), "r"(b[0]), "r"(b[1]));
}
#define CP16(dst, src) asm volatile("cp.async.cg.shared.global [%0], [%1], 16;" :: "r"(dst), "l"(src) : "memory")
#define CP_COMMIT()    asm volatile("cp.async.commit_group;" ::: "memory")
#define CP_WAIT(n)     asm volatile("cp.async.wait_group %0;" :: "n"(n) : "memory")
// Drop a dirty L2 line WITHOUT write-back (scratch is dead after attn reads it)
#define L2_DISCARD(p)  asm volatile("discard.global.L2 [%0], 128;" :: "l"(p) : "memory")

#define XPH 136
#define WPH 72
#define PH  136
#define PROJ_SMEM (64*XPH*2 + 3*64*WPH*2)
#define ATTN_SMEM (2 * 128 * PH * 2)
#define CMB_SMEM  (ATTN_SMEM > PROJ_SMEM ? ATTN_SMEM : PROJ_SMEM)

// ---------------------------------------------------------------------------
// proj body: q/k/v = W @ x + b (fp16 HMMA), q pre-scaled; also stores fp16 x.
// ---------------------------------------------------------------------------
__device__ __forceinline__ void proj_body(
    const float* __restrict__ x,
    const float* __restrict__ Wq, const float* __restrict__ bq,
    const float* __restrict__ Wk, const float* __restrict__ bk,
    const float* __restrict__ Wv, const float* __restrict__ bv,
    int b, int px0, __half* smp)
{
    __half* Xs = smp;
    __half* Ws = smp + 64 * XPH;
    const uint32_t smb = smem_u32(smp);
    const uint32_t XsB = smb, WsB = smb + 64 * XPH * 2;

    const int tid  = threadIdx.x;
    const int w    = tid >> 5;
    const int lane = tid & 31;
    const int g    = lane >> 2;
    const int tg   = lane & 3;
    const int m0   = (w & 3) * 16;
    const int n0   = (w >> 2) * 64;

    // Fill X tile (fp32 -> fp16) and write the fp16 x sidecar for attn
    const float* xb = x + (size_t)b * C_ * HW_ + px0;
    __half* xhb = g_xh + (size_t)b * C_ * HW_ + px0;
    #pragma unroll 4
    for (int e = tid; e < 2048; e += 256) {
        int r = e >> 5, c4 = e & 31;
        float4 v = *((const float4*)(xb + r * HW_) + c4);
        uint2 hv = make_uint2(packh2(v.x, v.y), packh2(v.z, v.w));
        *(uint2*)(Xs + r * XPH + c4 * 4) = hv;
        *(uint2*)(xhb + r * HW_ + c4 * 4) = hv;
    }
    #pragma unroll 4
    for (int e = tid; e < 3 * 2048; e += 256) {
        int mtx = e >> 11, i = e & 2047;
        int o = i >> 5, c2 = i & 31;
        const float* Wm = (mtx == 0) ? Wq : (mtx == 1) ? Wk : Wv;
        float2 wv = *((const float2*)(Wm + o * 64) + c2);
        *(uint32_t*)(Ws + mtx * 64 * WPH + o * WPH + c2 * 2) = packh2(wv.x, wv.y);
    }
    __syncthreads();

    const int rsel = lane & 15;
    const int csel = (lane & 16) >> 1;

    #pragma unroll
    for (int mtx = 0; mtx < 3; mtx++) {
        const uint32_t WtB = WsB + (uint32_t)mtx * 64 * WPH * 2;
        float acc[8][4];
        #pragma unroll
        for (int nt = 0; nt < 8; nt++)
            #pragma unroll
            for (int j = 0; j < 4; j++) acc[nt][j] = 0.f;

        #pragma unroll
        for (int k0 = 0; k0 < 64; k0 += 16) {
            uint32_t a[4];
            ldmx4(a, WtB + (uint32_t)((m0 + rsel) * WPH + k0 + csel) * 2);
            #pragma unroll
            for (int ntp = 0; ntp < 4; ntp++) {
                uint32_t bb[4];
                ldmx4t(bb, XsB + (uint32_t)((k0 + rsel) * XPH + n0 + ntp * 16 + csel) * 2);
                mma_f16(acc[2 * ntp],     a, bb);
                mma_f16(acc[2 * ntp + 1], a, bb + 2);
            }
        }

        const float* bm = (mtx == 0) ? bq : (mtx == 1) ? bk : bv;
        __half* gout = ((mtx == 0) ? g_q : (mtx == 1) ? g_k : g_v);
        const float sc = (mtx == 0) ? 0.0078125f : 1.0f;   // 1/sqrt(HW) into q
        float bias0 = bm[m0 + g], bias1 = bm[m0 + g + 8];
        __half* orow0 = gout + ((size_t)b * C_ + m0 + g) * HW_ + px0;
        __half* orow1 = orow0 + 8 * HW_;
        #pragma unroll
        for (int nt = 0; nt < 8; nt++) {
            int col = n0 + nt * 8 + 2 * tg;
            *(uint32_t*)(orow0 + col) =
                packh2((acc[nt][0] + bias0) * sc, (acc[nt][1] + bias0) * sc);
            *(uint32_t*)(orow1 + col) =
                packh2((acc[nt][2] + bias1) * sc, (acc[nt][3] + bias1) * sc);
        }
    }
}

// ---------------------------------------------------------------------------
// attn body: per-(b,c) slice, fp16 HMMA, register P, fp16 residual sidecar.
// Q fragments double-buffered (2 stages, 8 regs) instead of fully resident
// (32 regs) -> drops peak live set so the combo union fits 128 w/o spills.
// ---------------------------------------------------------------------------
#define LOADQ(dst, k0) do { \
    dst[0] = *(const uint32_t*)(qg + (m0 + g) * 128 + (k0) + 2 * tg); \
    dst[1] = *(const uint32_t*)(qg + (m0 + g + 8) * 128 + (k0) + 2 * tg); \
    dst[2] = *(const uint32_t*)(qg + (m0 + g) * 128 + (k0) + 8 + 2 * tg); \
    dst[3] = *(const uint32_t*)(qg + (m0 + g + 8) * 128 + (k0) + 8 + 2 * tg); \
} while (0)

__device__ __forceinline__ void attn_body(
    float* __restrict__ out, int bc, __half* sma)
{
    const uint32_t smb = smem_u32(sma);
    const uint32_t KsB = smb, VsB = smb + 128 * PH * 2;

    const size_t base = (size_t)bc * HW_;
    const int tid  = threadIdx.x;
    const int wid  = tid >> 5;
    const int lane = tid & 31;
    const int g    = lane >> 2;
    const int tg   = lane & 3;
    const int m0   = wid * 16;
    const int rsel = lane & 15;
    const int csel = (lane & 16) >> 1;

    // Async fills: K -> group0, V -> group1
    const uint4* kg = (const uint4*)(g_k + base);
    const uint4* vg = (const uint4*)(g_v + base);
    #pragma unroll
    for (int e = tid; e < 2048; e += 256) {
        uint32_t off = (uint32_t)((e >> 4) * PH + (e & 15) * 8) * 2;
        CP16(KsB + off, kg + e);
    }
    CP_COMMIT();
    #pragma unroll
    for (int e = tid; e < 2048; e += 256) {
        uint32_t off = (uint32_t)((e >> 4) * PH + (e & 15) * 8) * 2;
        CP16(VsB + off, vg + e);
    }
    CP_COMMIT();

    // Q: double-buffered A-fragments from gmem/L2 (2 stages in flight)
    const __half* qg = g_q + base;
    uint32_t aqc[4], aqn[4];
    LOADQ(aqc, 0);       // stage 0 in flight while K lands

    CP_WAIT(1);          // K landed
    __syncthreads();

    // ---- MM1: S = Q.K^T (q pre-scaled) ----
    float acc[16][4];
    #pragma unroll
    for (int nt = 0; nt < 16; nt++)
        #pragma unroll
        for (int j = 0; j < 4; j++) acc[nt][j] = 0.f;

    #pragma unroll
    for (int ks = 0; ks < 8; ks++) {
        const int k0 = ks * 16;
        if (ks < 7) LOADQ(aqn, k0 + 16);   // prefetch next stage under mmas
        #pragma unroll
        for (int ntp = 0; ntp < 8; ntp++) {
            uint32_t kb[4];
            ldmx4(kb, KsB + (uint32_t)((ntp * 16 + csel + (lane & 7)) * PH + k0 + (lane & 8)) * 2);
            mma_f16(acc[2 * ntp],     aqc, kb);
            mma_f16(acc[2 * ntp + 1], aqc, kb + 2);
        }
        #pragma unroll
        for (int j = 0; j < 4; j++) aqc[j] = aqn[j];
    }

    // ---- softmax; P packed to fp16 in regs ----
    float sum0 = 0.f, sum1 = 0.f;
    uint32_t ph[16][2];
    #pragma unroll
    for (int nt = 0; nt < 16; nt++) {
        float e0 = __expf(acc[nt][0]);
        float e1 = __expf(acc[nt][1]);
        float e2 = __expf(acc[nt][2]);
        float e3 = __expf(acc[nt][3]);
        sum0 += e0 + e1;  sum1 += e2 + e3;
        ph[nt][0] = packh2(e0, e1);
        ph[nt][1] = packh2(e2, e3);
    }
    sum0 += __shfl_xor_sync(0xffffffffu, sum0, 1);
    sum0 += __shfl_xor_sync(0xffffffffu, sum0, 2);
    sum1 += __shfl_xor_sync(0xffffffffu, sum1, 1);
    sum1 += __shfl_xor_sync(0xffffffffu, sum1, 2);
    const float rin0 = 1.0f / sum0, rin1 = 1.0f / sum1;

    CP_WAIT(0);          // V landed
    __syncthreads();

    // ---- MM2: O = P.V + x (fp16 sidecar residual) ----
    const __half* xh = g_xh + base;
    float* og = out + base;
    #pragma unroll
    for (int hf = 0; hf < 2; hf++) {
        const int w00 = hf * 64;

        // Prefetch fp16 residuals for this half (hidden under mma chain)
        __half2 xv[16];
        #pragma unroll
        for (int wt = 0; wt < 8; wt++) {
            int col = w00 + wt * 8 + 2 * tg;
            xv[2 * wt]     = *(const __half2*)(xh + (m0 + g) * W_ + col);
            xv[2 * wt + 1] = *(const __half2*)(xh + (m0 + g + 8) * W_ + col);
        }

        float o[8][4];
        #pragma unroll
        for (int wt = 0; wt < 8; wt++)
            #pragma unroll
            for (int j = 0; j < 4; j++) o[wt][j] = 0.f;

        #pragma unroll
        for (int s = 0; s < 8; s++) {
            const int k0 = s * 16;
            uint32_t a[4] = { ph[2*s][0], ph[2*s][1], ph[2*s+1][0], ph[2*s+1][1] };
            #pragma unroll
            for (int wtp = 0; wtp < 4; wtp++) {
                uint32_t vb[4];
                ldmx4t(vb, VsB + (uint32_t)((k0 + rsel) * PH + w00 + wtp * 16 + csel) * 2);
                mma_f16(o[2 * wtp],     a, vb);
                mma_f16(o[2 * wtp + 1], a, vb + 2);
            }
        }

        #pragma unroll
        for (int wt = 0; wt < 8; wt++) {
            int col = w00 + wt * 8 + 2 * tg;
            float2 f0 = __half22float2(xv[2 * wt]);
            float2 f1 = __half22float2(xv[2 * wt + 1]);
            *(float2*)(og + (m0 + g) * W_ + col) =
                make_float2(o[wt][0] * rin0 + f0.x, o[wt][1] * rin0 + f0.y);
            *(float2*)(og + (m0 + g + 8) * W_ + col) =
                make_float2(o[wt][2] * rin1 + f1.x, o[wt][3] * rin1 + f1.y);
        }
    }

    // ---- discard dead scratch lines from L2 (skip the DRAM write-back) ----
    __syncthreads();
    {
        const char* pq = (const char*)(g_q  + base);
        const char* pk = (const char*)(g_k  + base);
        const char* pv = (const char*)(g_v  + base);
        const char* px = (const char*)(g_xh + base);
        const int i = tid;
        L2_DISCARD(pq + i * 128);
        L2_DISCARD(pk + i * 128);
        L2_DISCARD(pv + i * 128);
        L2_DISCARD(px + i * 128);
    }
}

// ---------------------------------------------------------------------------
// Combo kernel: first n_attn CTAs run attn(group L-1), rest run proj(group L).
// ---------------------------------------------------------------------------
__global__ __launch_bounds__(256, 2) void combo_kernel(
    const float* __restrict__ x,
    const float* __restrict__ Wq, const float* __restrict__ bq,
    const float* __restrict__ Wk, const float* __restrict__ bk,
    const float* __restrict__ Wv, const float* __restrict__ bv,
    float* __restrict__ out,
    int proj_b0, int attn_bc0, int n_attn)
{
    extern __shared__ __half smc[];
    const int bi = (int)blockIdx.x;
    if (bi < n_attn) {
        attn_body(out, attn_bc0 + bi, smc);
    } else {
        const int pb = bi - n_attn;
        proj_body(x, Wq, bq, Wk, bk, Wv, bv,
                  proj_b0 + (pb >> 7), (pb & 127) * 128, smc);
    }
}

// ---------------------------------------------------------------------------
extern "C" void kernel_launch(void* const* d_in, const int* in_sizes, int n_in,
                              void* d_out, int out_size)
{
    const float* x  = (const float*)d_in[0];
    const float* Wq = (const float*)d_in[1];
    const float* bq = (const float*)d_in[2];
    const float* Wk = (const float*)d_in[3];
    const float* bk = (const float*)d_in[4];
    const float* Wv = (const float*)d_in[5];
    const float* bv = (const float*)d_in[6];
    float* out = (float*)d_out;

    cudaFuncSetAttribute(combo_kernel, cudaFuncAttributeMaxDynamicSharedMemorySize, CMB_SMEM);

    // Pipelined: launch L = attn(group L-1) || proj(group L)
    for (int L = 0; L <= NGRP; L++) {
        int n_proj = (L < NGRP) ? 512 : 0;
        int n_attn = (L > 0) ? 256 : 0;
        combo_kernel<<<n_proj + n_attn, 256, CMB_SMEM>>>(
            x, Wq, bq, Wk, bk, Wv, bv, out,
            L * GRP, (L - 1) * GRP * 64, n_attn);
    }
}

// round 15
// speedup vs baseline: 1.1915x; 1.0779x over previous
#include <cuda_runtime.h>
#include <cuda_fp16.h>
#include <cstdint>

#define B_ 32
#define C_ 64
#define H_ 128
#define W_ 128
#define HW_ (H_*W_)
#define NTOT_ (B_*C_*HW_)

#define GRP 8                 // batches per group (wave-quantization fix)
#define NGRP (B_/GRP)

// fp16 scratch: q/k/v projections + fp16 copy of x for the residual read
__device__ __half g_q[NTOT_];
__device__ __half g_k[NTOT_];
__device__ __half g_v[NTOT_];
__device__ __half g_xh[NTOT_];

// ---------------- helpers ----------------
__device__ __forceinline__ uint32_t smem_u32(const void* p) {
    uint32_t a;
    asm("{ .reg .u64 t; cvta.to.shared.u64 t, %1; cvt.u32.u64 %0, t; }" : "=r"(a) : "l"(p));
    return a;
}
__device__ __forceinline__ uint32_t packh2(float lo, float hi) {
    __half2 h = __floats2half2_rn(lo, hi);
    return *reinterpret_cast<uint32_t*>(&h);
}
__device__ __forceinline__ void ldmx4(uint32_t* r, uint32_t addr) {
    asm volatile("ldmatrix.sync.aligned.m8n8.x4.shared.b16 {%0,%1,%2,%3}, [%4];"
        : "=r"(r[0]), "=r"(r[1]), "=r"(r[2]), "=r"(r[3]) : "r"(addr));
}
__device__ __forceinline__ void ldmx4t(uint32_t* r, uint32_t addr) {
    asm volatile("ldmatrix.sync.aligned.m8n8.x4.trans.shared.b16 {%0,%1,%2,%3}, [%4];"
        : "=r"(r[0]), "=r"(r[1]), "=r"(r[2]), "=r"(r[3]) : "r"(addr));
}
__device__ __forceinline__ void mma_f16(float* d, const uint32_t* a, const uint32_t* b) {
    asm volatile("mma.sync.aligned.m16n8k16.row.col.f32.f16.f16.f32 "
        "{%0,%1,%2,%3}, {%4,%5,%6,%7}, {%8,%9}, {%0,%1,%2,%3};"
        : "+f"(d[0]), "+f"(d[1]), "+f"(d[2]), "+f"(d[3])
        : "r"(a[0]), "r"(a[1]), "r"(a[2]), "r"(a[3]), "r"(b[0]), "r"(b[1]));
}
#define CP16(dst, src) asm volatile("cp.async.cg.shared.global [%0], [%1], 16;" :: "r"(dst), "l"(src) : "memory")
#define CP_COMMIT()    asm volatile("cp.async.commit_group;" ::: "memory")
#define CP_WAIT(n)     asm volatile("cp.async.wait_group %0;" :: "n"(n) : "memory")
// Drop a dirty L2 line WITHOUT write-back (scratch is dead after attn reads it)
#define L2_DISCARD(p)  asm volatile("discard.global.L2 [%0], 128;" :: "l"(p) : "memory")

#define XPH 136
#define WPH 72
#define PH  136
#define PROJ_SMEM (64*XPH*2 + 3*64*WPH*2)
#define ATTN_SMEM (2 * 128 * PH * 2)
#define CMB_SMEM  (ATTN_SMEM > PROJ_SMEM ? ATTN_SMEM : PROJ_SMEM)

// ---------------------------------------------------------------------------
// proj body: q/k/v = W @ x + b (fp16 HMMA), q pre-scaled; also stores fp16 x.
// ---------------------------------------------------------------------------
__device__ __forceinline__ void proj_body(
    const float* __restrict__ x,
    const float* __restrict__ Wq, const float* __restrict__ bq,
    const float* __restrict__ Wk, const float* __restrict__ bk,
    const float* __restrict__ Wv, const float* __restrict__ bv,
    int b, int px0, __half* smp)
{
    __half* Xs = smp;
    __half* Ws = smp + 64 * XPH;
    const uint32_t smb = smem_u32(smp);
    const uint32_t XsB = smb, WsB = smb + 64 * XPH * 2;

    const int tid  = threadIdx.x;
    const int w    = tid >> 5;
    const int lane = tid & 31;
    const int g    = lane >> 2;
    const int tg   = lane & 3;
    const int m0   = (w & 3) * 16;
    const int n0   = (w >> 2) * 64;

    // Fill X tile (fp32 -> fp16) and write the fp16 x sidecar for attn
    const float* xb = x + (size_t)b * C_ * HW_ + px0;
    __half* xhb = g_xh + (size_t)b * C_ * HW_ + px0;
    #pragma unroll 4
    for (int e = tid; e < 2048; e += 256) {
        int r = e >> 5, c4 = e & 31;
        float4 v = *((const float4*)(xb + r * HW_) + c4);
        uint2 hv = make_uint2(packh2(v.x, v.y), packh2(v.z, v.w));
        *(uint2*)(Xs + r * XPH + c4 * 4) = hv;
        *(uint2*)(xhb + r * HW_ + c4 * 4) = hv;
    }
    #pragma unroll 4
    for (int e = tid; e < 3 * 2048; e += 256) {
        int mtx = e >> 11, i = e & 2047;
        int o = i >> 5, c2 = i & 31;
        const float* Wm = (mtx == 0) ? Wq : (mtx == 1) ? Wk : Wv;
        float2 wv = *((const float2*)(Wm + o * 64) + c2);
        *(uint32_t*)(Ws + mtx * 64 * WPH + o * WPH + c2 * 2) = packh2(wv.x, wv.y);
    }
    __syncthreads();

    const int rsel = lane & 15;
    const int csel = (lane & 16) >> 1;

    #pragma unroll
    for (int mtx = 0; mtx < 3; mtx++) {
        const uint32_t WtB = WsB + (uint32_t)mtx * 64 * WPH * 2;
        float acc[8][4];
        #pragma unroll
        for (int nt = 0; nt < 8; nt++)
            #pragma unroll
            for (int j = 0; j < 4; j++) acc[nt][j] = 0.f;

        #pragma unroll
        for (int k0 = 0; k0 < 64; k0 += 16) {
            uint32_t a[4];
            ldmx4(a, WtB + (uint32_t)((m0 + rsel) * WPH + k0 + csel) * 2);
            #pragma unroll
            for (int ntp = 0; ntp < 4; ntp++) {
                uint32_t bb[4];
                ldmx4t(bb, XsB + (uint32_t)((k0 + rsel) * XPH + n0 + ntp * 16 + csel) * 2);
                mma_f16(acc[2 * ntp],     a, bb);
                mma_f16(acc[2 * ntp + 1], a, bb + 2);
            }
        }

        const float* bm = (mtx == 0) ? bq : (mtx == 1) ? bk : bv;
        __half* gout = ((mtx == 0) ? g_q : (mtx == 1) ? g_k : g_v);
        const float sc = (mtx == 0) ? 0.0078125f : 1.0f;   // 1/sqrt(HW) into q
        float bias0 = bm[m0 + g], bias1 = bm[m0 + g + 8];
        __half* orow0 = gout + ((size_t)b * C_ + m0 + g) * HW_ + px0;
        __half* orow1 = orow0 + 8 * HW_;
        #pragma unroll
        for (int nt = 0; nt < 8; nt++) {
            int col = n0 + nt * 8 + 2 * tg;
            *(uint32_t*)(orow0 + col) =
                packh2((acc[nt][0] + bias0) * sc, (acc[nt][1] + bias0) * sc);
            *(uint32_t*)(orow1 + col) =
                packh2((acc[nt][2] + bias1) * sc, (acc[nt][3] + bias1) * sc);
        }
    }
}

// ---------------------------------------------------------------------------
// attn body: per-(b,c) slice, fp16 HMMA, register P, fp16 residual sidecar.
// ---------------------------------------------------------------------------
#define LOADQ(dst, k0) do { \
    dst[0] = *(const uint32_t*)(qg + (m0 + g) * 128 + (k0) + 2 * tg); \
    dst[1] = *(const uint32_t*)(qg + (m0 + g + 8) * 128 + (k0) + 2 * tg); \
    dst[2] = *(const uint32_t*)(qg + (m0 + g) * 128 + (k0) + 8 + 2 * tg); \
    dst[3] = *(const uint32_t*)(qg + (m0 + g + 8) * 128 + (k0) + 8 + 2 * tg); \
} while (0)

__device__ __forceinline__ void attn_body(
    float* __restrict__ out, int bc, __half* sma)
{
    const uint32_t smb = smem_u32(sma);
    const uint32_t KsB = smb, VsB = smb + 128 * PH * 2;

    const size_t base = (size_t)bc * HW_;
    const int tid  = threadIdx.x;
    const int wid  = tid >> 5;
    const int lane = tid & 31;
    const int g    = lane >> 2;
    const int tg   = lane & 3;
    const int m0   = wid * 16;
    const int rsel = lane & 15;
    const int csel = (lane & 16) >> 1;

    // Async fills: K -> group0, V -> group1
    const uint4* kg = (const uint4*)(g_k + base);
    const uint4* vg = (const uint4*)(g_v + base);
    #pragma unroll
    for (int e = tid; e < 2048; e += 256) {
        uint32_t off = (uint32_t)((e >> 4) * PH + (e & 15) * 8) * 2;
        CP16(KsB + off, kg + e);
    }
    CP_COMMIT();
    #pragma unroll
    for (int e = tid; e < 2048; e += 256) {
        uint32_t off = (uint32_t)((e >> 4) * PH + (e & 15) * 8) * 2;
        CP16(VsB + off, vg + e);
    }
    CP_COMMIT();

    // Q: double-buffered A-fragments from gmem/L2 (2 stages in flight)
    const __half* qg = g_q + base;
    uint32_t aqc[4], aqn[4];
    LOADQ(aqc, 0);       // stage 0 in flight while K lands

    CP_WAIT(1);          // K landed
    __syncthreads();

    // ---- MM1: S = Q.K^T (q pre-scaled) ----
    float acc[16][4];
    #pragma unroll
    for (int nt = 0; nt < 16; nt++)
        #pragma unroll
        for (int j = 0; j < 4; j++) acc[nt][j] = 0.f;

    #pragma unroll
    for (int ks = 0; ks < 8; ks++) {
        const int k0 = ks * 16;
        if (ks < 7) LOADQ(aqn, k0 + 16);   // prefetch next stage under mmas
        #pragma unroll
        for (int ntp = 0; ntp < 8; ntp++) {
            uint32_t kb[4];
            ldmx4(kb, KsB + (uint32_t)((ntp * 16 + csel + (lane & 7)) * PH + k0 + (lane & 8)) * 2);
            mma_f16(acc[2 * ntp],     aqc, kb);
            mma_f16(acc[2 * ntp + 1], aqc, kb + 2);
        }
        #pragma unroll
        for (int j = 0; j < 4; j++) aqc[j] = aqn[j];
    }

    // ---- softmax; P packed to fp16 in regs ----
    float sum0 = 0.f, sum1 = 0.f;
    uint32_t ph[16][2];
    #pragma unroll
    for (int nt = 0; nt < 16; nt++) {
        float e0 = __expf(acc[nt][0]);
        float e1 = __expf(acc[nt][1]);
        float e2 = __expf(acc[nt][2]);
        float e3 = __expf(acc[nt][3]);
        sum0 += e0 + e1;  sum1 += e2 + e3;
        ph[nt][0] = packh2(e0, e1);
        ph[nt][1] = packh2(e2, e3);
    }
    sum0 += __shfl_xor_sync(0xffffffffu, sum0, 1);
    sum0 += __shfl_xor_sync(0xffffffffu, sum0, 2);
    sum1 += __shfl_xor_sync(0xffffffffu, sum1, 1);
    sum1 += __shfl_xor_sync(0xffffffffu, sum1, 2);
    const float rin0 = 1.0f / sum0, rin1 = 1.0f / sum1;

    CP_WAIT(0);          // V landed
    __syncthreads();

    // ---- MM2: O = P.V + x (fp16 sidecar residual) ----
    const __half* xh = g_xh + base;
    float* og = out + base;
    #pragma unroll
    for (int hf = 0; hf < 2; hf++) {
        const int w00 = hf * 64;

        // Prefetch fp16 residuals for this half (hidden under mma chain)
        __half2 xv[16];
        #pragma unroll
        for (int wt = 0; wt < 8; wt++) {
            int col = w00 + wt * 8 + 2 * tg;
            xv[2 * wt]     = *(const __half2*)(xh + (m0 + g) * W_ + col);
            xv[2 * wt + 1] = *(const __half2*)(xh + (m0 + g + 8) * W_ + col);
        }

        float o[8][4];
        #pragma unroll
        for (int wt = 0; wt < 8; wt++)
            #pragma unroll
            for (int j = 0; j < 4; j++) o[wt][j] = 0.f;

        #pragma unroll
        for (int s = 0; s < 8; s++) {
            const int k0 = s * 16;
            uint32_t a[4] = { ph[2*s][0], ph[2*s][1], ph[2*s+1][0], ph[2*s+1][1] };
            #pragma unroll
            for (int wtp = 0; wtp < 4; wtp++) {
                uint32_t vb[4];
                ldmx4t(vb, VsB + (uint32_t)((k0 + rsel) * PH + w00 + wtp * 16 + csel) * 2);
                mma_f16(o[2 * wtp],     a, vb);
                mma_f16(o[2 * wtp + 1], a, vb + 2);
            }
        }

        #pragma unroll
        for (int wt = 0; wt < 8; wt++) {
            int col = w00 + wt * 8 + 2 * tg;
            float2 f0 = __half22float2(xv[2 * wt]);
            float2 f1 = __half22float2(xv[2 * wt + 1]);
            *(float2*)(og + (m0 + g) * W_ + col) =
                make_float2(o[wt][0] * rin0 + f0.x, o[wt][1] * rin0 + f0.y);
            *(float2*)(og + (m0 + g + 8) * W_ + col) =
                make_float2(o[wt][2] * rin1 + f1.x, o[wt][3] * rin1 + f1.y);
        }
    }

    // ---- discard dead scratch lines from L2 (skip the DRAM write-back) ----
    __syncthreads();
    {
        const char* pq = (const char*)(g_q  + base);
        const char* pk = (const char*)(g_k  + base);
        const char* pv = (const char*)(g_v  + base);
        const char* px = (const char*)(g_xh + base);
        const int i = tid;
        L2_DISCARD(pq + i * 128);
        L2_DISCARD(pk + i * 128);
        L2_DISCARD(pv + i * 128);
        L2_DISCARD(px + i * 128);
    }
}

// ---------------------------------------------------------------------------
// Combo kernel: first n_attn CTAs run attn(group L-1), rest run proj(group L).
// ---------------------------------------------------------------------------
__global__ __launch_bounds__(256, 2) void combo_kernel(
    const float* __restrict__ x,
    const float* __restrict__ Wq, const float* __restrict__ bq,
    const float* __restrict__ Wk, const float* __restrict__ bk,
    const float* __restrict__ Wv, const float* __restrict__ bv,
    float* __restrict__ out,
    int proj_b0, int attn_bc0, int n_attn)
{
    extern __shared__ __half smc[];
    const int bi = (int)blockIdx.x;
    if (bi < n_attn) {
        attn_body(out, attn_bc0 + bi, smc);
    } else {
        const int pb = bi - n_attn;
        proj_body(x, Wq, bq, Wk, bk, Wv, bv,
                  proj_b0 + (pb >> 7), (pb & 127) * 128, smc);
    }
}

// ---------------------------------------------------------------------------
extern "C" void kernel_launch(void* const* d_in, const int* in_sizes, int n_in,
                              void* d_out, int out_size)
{
    const float* x  = (const float*)d_in[0];
    const float* Wq = (const float*)d_in[1];
    const float* bq = (const float*)d_in[2];
    const float* Wk = (const float*)d_in[3];
    const float* bk = (const float*)d_in[4];
    const float* Wv = (const float*)d_in[5];
    const float* bv = (const float*)d_in[6];
    float* out = (float*)d_out;

    cudaFuncSetAttribute(combo_kernel, cudaFuncAttributeMaxDynamicSharedMemorySize, CMB_SMEM);

    // Pipelined: launch L = attn(group L-1) || proj(group L); GRP=8 halves
    // the launch count and cuts partial-wave waste (2.59 -> 5.19 waves).
    for (int L = 0; L <= NGRP; L++) {
        int n_proj = (L < NGRP) ? GRP * 128 : 0;
        int n_attn = (L > 0) ? GRP * 64 : 0;
        combo_kernel<<<n_proj + n_attn, 256, CMB_SMEM>>>(
            x, Wq, bq, Wk, bk, Wv, bv, out,
            L * GRP, (L - 1) * GRP * 64, n_attn);
    }
}

// round 16
// speedup vs baseline: 1.1984x; 1.0058x over previous
#include <cuda_runtime.h>
#include <cuda_fp16.h>
#include <cstdint>

#define B_ 32
#define C_ 64
#define H_ 128
#define W_ 128
#define HW_ (H_*W_)
#define NTOT_ (B_*C_*HW_)

// fp16 scratch: q/k/v projections + fp16 copy of x for the residual read
__device__ __half g_q[NTOT_];
__device__ __half g_k[NTOT_];
__device__ __half g_v[NTOT_];
__device__ __half g_xh[NTOT_];

// ---------------- helpers ----------------
__device__ __forceinline__ uint32_t smem_u32(const void* p) {
    uint32_t a;
    asm("{ .reg .u64 t; cvta.to.shared.u64 t, %1; cvt.u32.u64 %0, t; }" : "=r"(a) : "l"(p));
    return a;
}
__device__ __forceinline__ uint32_t packh2(float lo, float hi) {
    __half2 h = __floats2half2_rn(lo, hi);
    return *reinterpret_cast<uint32_t*>(&h);
}
__device__ __forceinline__ void ldmx4(uint32_t* r, uint32_t addr) {
    asm volatile("ldmatrix.sync.aligned.m8n8.x4.shared.b16 {%0,%1,%2,%3}, [%4];"
        : "=r"(r[0]), "=r"(r[1]), "=r"(r[2]), "=r"(r[3]) : "r"(addr));
}
__device__ __forceinline__ void ldmx4t(uint32_t* r, uint32_t addr) {
    asm volatile("ldmatrix.sync.aligned.m8n8.x4.trans.shared.b16 {%0,%1,%2,%3}, [%4];"
        : "=r"(r[0]), "=r"(r[1]), "=r"(r[2]), "=r"(r[3]) : "r"(addr));
}
__device__ __forceinline__ void mma_f16(float* d, const uint32_t* a, const uint32_t* b) {
    asm volatile("mma.sync.aligned.m16n8k16.row.col.f32.f16.f16.f32 "
        "{%0,%1,%2,%3}, {%4,%5,%6,%7}, {%8,%9}, {%0,%1,%2,%3};"
        : "+f"(d[0]), "+f"(d[1]), "+f"(d[2]), "+f"(d[3])
        : "r"(a[0]), "r"(a[1]), "r"(a[2]), "r"(a[3]), "r"(b[0]), "r"(b[1]));
}
#define CP16(dst, src) asm volatile("cp.async.cg.shared.global [%0], [%1], 16;" :: "r"(dst), "l"(src) : "memory")
#define CP_COMMIT()    asm volatile("cp.async.commit_group;" ::: "memory")
#define CP_WAIT(n)     asm volatile("cp.async.wait_group %0;" :: "n"(n) : "memory")
// Drop a dirty L2 line WITHOUT write-back (scratch is dead once it's in smem/regs)
#define L2_DISCARD(p)  asm volatile("discard.global.L2 [%0], 128;" :: "l"(p) : "memory")

#define XPH 136
#define WPH 72
#define PH  136
#define PROJ_SMEM (64*XPH*2 + 3*64*WPH*2)
#define ATTN_SMEM (2 * 128 * PH * 2)
#define CMB_SMEM  (ATTN_SMEM > PROJ_SMEM ? ATTN_SMEM : PROJ_SMEM)

// ---------------------------------------------------------------------------
// proj body: q/k/v = W @ x + b (fp16 HMMA), q pre-scaled; also stores fp16 x.
// ---------------------------------------------------------------------------
__device__ __forceinline__ void proj_body(
    const float* __restrict__ x,
    const float* __restrict__ Wq, const float* __restrict__ bq,
    const float* __restrict__ Wk, const float* __restrict__ bk,
    const float* __restrict__ Wv, const float* __restrict__ bv,
    int b, int px0, __half* smp)
{
    __half* Xs = smp;
    __half* Ws = smp + 64 * XPH;
    const uint32_t smb = smem_u32(smp);
    const uint32_t XsB = smb, WsB = smb + 64 * XPH * 2;

    const int tid  = threadIdx.x;
    const int w    = tid >> 5;
    const int lane = tid & 31;
    const int g    = lane >> 2;
    const int tg   = lane & 3;
    const int m0   = (w & 3) * 16;
    const int n0   = (w >> 2) * 64;

    // Fill X tile (fp32 -> fp16) and write the fp16 x sidecar for attn
    const float* xb = x + (size_t)b * C_ * HW_ + px0;
    __half* xhb = g_xh + (size_t)b * C_ * HW_ + px0;
    #pragma unroll 4
    for (int e = tid; e < 2048; e += 256) {
        int r = e >> 5, c4 = e & 31;
        float4 v = *((const float4*)(xb + r * HW_) + c4);
        uint2 hv = make_uint2(packh2(v.x, v.y), packh2(v.z, v.w));
        *(uint2*)(Xs + r * XPH + c4 * 4) = hv;
        *(uint2*)(xhb + r * HW_ + c4 * 4) = hv;
    }
    #pragma unroll 4
    for (int e = tid; e < 3 * 2048; e += 256) {
        int mtx = e >> 11, i = e & 2047;
        int o = i >> 5, c2 = i & 31;
        const float* Wm = (mtx == 0) ? Wq : (mtx == 1) ? Wk : Wv;
        float2 wv = *((const float2*)(Wm + o * 64) + c2);
        *(uint32_t*)(Ws + mtx * 64 * WPH + o * WPH + c2 * 2) = packh2(wv.x, wv.y);
    }
    __syncthreads();

    const int rsel = lane & 15;
    const int csel = (lane & 16) >> 1;

    #pragma unroll
    for (int mtx = 0; mtx < 3; mtx++) {
        const uint32_t WtB = WsB + (uint32_t)mtx * 64 * WPH * 2;
        float acc[8][4];
        #pragma unroll
        for (int nt = 0; nt < 8; nt++)
            #pragma unroll
            for (int j = 0; j < 4; j++) acc[nt][j] = 0.f;

        #pragma unroll
        for (int k0 = 0; k0 < 64; k0 += 16) {
            uint32_t a[4];
            ldmx4(a, WtB + (uint32_t)((m0 + rsel) * WPH + k0 + csel) * 2);
            #pragma unroll
            for (int ntp = 0; ntp < 4; ntp++) {
                uint32_t bb[4];
                ldmx4t(bb, XsB + (uint32_t)((k0 + rsel) * XPH + n0 + ntp * 16 + csel) * 2);
                mma_f16(acc[2 * ntp],     a, bb);
                mma_f16(acc[2 * ntp + 1], a, bb + 2);
            }
        }

        const float* bm = (mtx == 0) ? bq : (mtx == 1) ? bk : bv;
        __half* gout = ((mtx == 0) ? g_q : (mtx == 1) ? g_k : g_v);
        const float sc = (mtx == 0) ? 0.0078125f : 1.0f;   // 1/sqrt(HW) into q
        float bias0 = bm[m0 + g], bias1 = bm[m0 + g + 8];
        __half* orow0 = gout + ((size_t)b * C_ + m0 + g) * HW_ + px0;
        __half* orow1 = orow0 + 8 * HW_;
        #pragma unroll
        for (int nt = 0; nt < 8; nt++) {
            int col = n0 + nt * 8 + 2 * tg;
            *(uint32_t*)(orow0 + col) =
                packh2((acc[nt][0] + bias0) * sc, (acc[nt][1] + bias0) * sc);
            *(uint32_t*)(orow1 + col) =
                packh2((acc[nt][2] + bias1) * sc, (acc[nt][3] + bias1) * sc);
        }
    }
}

// ---------------------------------------------------------------------------
// attn body: per-(b,c) slice, fp16 HMMA, register P, fp16 residual sidecar.
// Dead scratch lines discarded from L2 as early as legal to free the window.
// ---------------------------------------------------------------------------
#define LOADQ(dst, k0) do { \
    dst[0] = *(const uint32_t*)(qg + (m0 + g) * 128 + (k0) + 2 * tg); \
    dst[1] = *(const uint32_t*)(qg + (m0 + g + 8) * 128 + (k0) + 2 * tg); \
    dst[2] = *(const uint32_t*)(qg + (m0 + g) * 128 + (k0) + 8 + 2 * tg); \
    dst[3] = *(const uint32_t*)(qg + (m0 + g + 8) * 128 + (k0) + 8 + 2 * tg); \
} while (0)

__device__ __forceinline__ void attn_body(
    float* __restrict__ out, int bc, __half* sma)
{
    const uint32_t smb = smem_u32(sma);
    const uint32_t KsB = smb, VsB = smb + 128 * PH * 2;

    const size_t base = (size_t)bc * HW_;
    const int tid  = threadIdx.x;
    const int wid  = tid >> 5;
    const int lane = tid & 31;
    const int g    = lane >> 2;
    const int tg   = lane & 3;
    const int m0   = wid * 16;
    const int rsel = lane & 15;
    const int csel = (lane & 16) >> 1;

    // Async fills: K -> group0, V -> group1
    const uint4* kg = (const uint4*)(g_k + base);
    const uint4* vg = (const uint4*)(g_v + base);
    #pragma unroll
    for (int e = tid; e < 2048; e += 256) {
        uint32_t off = (uint32_t)((e >> 4) * PH + (e & 15) * 8) * 2;
        CP16(KsB + off, kg + e);
    }
    CP_COMMIT();
    #pragma unroll
    for (int e = tid; e < 2048; e += 256) {
        uint32_t off = (uint32_t)((e >> 4) * PH + (e & 15) * 8) * 2;
        CP16(VsB + off, vg + e);
    }
    CP_COMMIT();

    // Q: double-buffered A-fragments from gmem/L2 (2 stages in flight)
    const __half* qg = g_q + base;
    uint32_t aqc[4], aqn[4];
    LOADQ(aqc, 0);       // stage 0 in flight while K lands

    CP_WAIT(1);          // K landed (in smem)
    __syncthreads();
    // K gmem lines are dead now — drop them from L2 without write-back
    L2_DISCARD((const char*)(g_k + base) + tid * 128);

    // ---- MM1: S = Q.K^T (q pre-scaled) ----
    float acc[16][4];
    #pragma unroll
    for (int nt = 0; nt < 16; nt++)
        #pragma unroll
        for (int j = 0; j < 4; j++) acc[nt][j] = 0.f;

    #pragma unroll
    for (int ks = 0; ks < 8; ks++) {
        const int k0 = ks * 16;
        if (ks < 7) LOADQ(aqn, k0 + 16);   // prefetch next stage under mmas
        #pragma unroll
        for (int ntp = 0; ntp < 8; ntp++) {
            uint32_t kb[4];
            ldmx4(kb, KsB + (uint32_t)((ntp * 16 + csel + (lane & 7)) * PH + k0 + (lane & 8)) * 2);
            mma_f16(acc[2 * ntp],     aqc, kb);
            mma_f16(acc[2 * ntp + 1], aqc, kb + 2);
        }
        #pragma unroll
        for (int j = 0; j < 4; j++) aqc[j] = aqn[j];
    }

    // ---- softmax; P packed to fp16 in regs ----
    float sum0 = 0.f, sum1 = 0.f;
    uint32_t ph[16][2];
    #pragma unroll
    for (int nt = 0; nt < 16; nt++) {
        float e0 = __expf(acc[nt][0]);
        float e1 = __expf(acc[nt][1]);
        float e2 = __expf(acc[nt][2]);
        float e3 = __expf(acc[nt][3]);
        sum0 += e0 + e1;  sum1 += e2 + e3;
        ph[nt][0] = packh2(e0, e1);
        ph[nt][1] = packh2(e2, e3);
    }
    sum0 += __shfl_xor_sync(0xffffffffu, sum0, 1);
    sum0 += __shfl_xor_sync(0xffffffffu, sum0, 2);
    sum1 += __shfl_xor_sync(0xffffffffu, sum1, 1);
    sum1 += __shfl_xor_sync(0xffffffffu, sum1, 2);
    const float rin0 = 1.0f / sum0, rin1 = 1.0f / sum1;

    CP_WAIT(0);          // V landed (in smem)
    __syncthreads();
    // Q fully consumed by all warps (barrier above); V gmem lines dead too
    L2_DISCARD((const char*)(g_q + base) + tid * 128);
    L2_DISCARD((const char*)(g_v + base) + tid * 128);

    // ---- MM2: O = P.V + x (fp16 sidecar residual) ----
    const __half* xh = g_xh + base;
    float* og = out + base;
    #pragma unroll
    for (int hf = 0; hf < 2; hf++) {
        const int w00 = hf * 64;

        // Prefetch fp16 residuals for this half (hidden under mma chain)
        __half2 xv[16];
        #pragma unroll
        for (int wt = 0; wt < 8; wt++) {
            int col = w00 + wt * 8 + 2 * tg;
            xv[2 * wt]     = *(const __half2*)(xh + (m0 + g) * W_ + col);
            xv[2 * wt + 1] = *(const __half2*)(xh + (m0 + g + 8) * W_ + col);
        }

        float o[8][4];
        #pragma unroll
        for (int wt = 0; wt < 8; wt++)
            #pragma unroll
            for (int j = 0; j < 4; j++) o[wt][j] = 0.f;

        #pragma unroll
        for (int s = 0; s < 8; s++) {
            const int k0 = s * 16;
            uint32_t a[4] = { ph[2*s][0], ph[2*s][1], ph[2*s+1][0], ph[2*s+1][1] };
            #pragma unroll
            for (int wtp = 0; wtp < 4; wtp++) {
                uint32_t vb[4];
                ldmx4t(vb, VsB + (uint32_t)((k0 + rsel) * PH + w00 + wtp * 16 + csel) * 2);
                mma_f16(o[2 * wtp],     a, vb);
                mma_f16(o[2 * wtp + 1], a, vb + 2);
            }
        }

        #pragma unroll
        for (int wt = 0; wt < 8; wt++) {
            int col = w00 + wt * 8 + 2 * tg;
            float2 f0 = __half22float2(xv[2 * wt]);
            float2 f1 = __half22float2(xv[2 * wt + 1]);
            *(float2*)(og + (m0 + g) * W_ + col) =
                make_float2(o[wt][0] * rin0 + f0.x, o[wt][1] * rin0 + f0.y);
            *(float2*)(og + (m0 + g + 8) * W_ + col) =
                make_float2(o[wt][2] * rin1 + f1.x, o[wt][3] * rin1 + f1.y);
        }
    }

    // xh fully consumed by all warps after this barrier
    __syncthreads();
    L2_DISCARD((const char*)(g_xh + base) + tid * 128);
}

// ---------------------------------------------------------------------------
// Combo kernel: first n_attn CTAs run attn(prev group), rest run proj(cur).
// ---------------------------------------------------------------------------
__global__ __launch_bounds__(256, 2) void combo_kernel(
    const float* __restrict__ x,
    const float* __restrict__ Wq, const float* __restrict__ bq,
    const float* __restrict__ Wk, const float* __restrict__ bk,
    const float* __restrict__ Wv, const float* __restrict__ bv,
    float* __restrict__ out,
    int proj_b0, int attn_bc0, int n_attn)
{
    extern __shared__ __half smc[];
    const int bi = (int)blockIdx.x;
    if (bi < n_attn) {
        attn_body(out, attn_bc0 + bi, smc);
    } else {
        const int pb = bi - n_attn;
        proj_body(x, Wq, bq, Wk, bk, Wv, bv,
                  proj_b0 + (pb >> 7), (pb & 127) * 128, smc);
    }
}

// ---------------------------------------------------------------------------
extern "C" void kernel_launch(void* const* d_in, const int* in_sizes, int n_in,
                              void* d_out, int out_size)
{
    const float* x  = (const float*)d_in[0];
    const float* Wq = (const float*)d_in[1];
    const float* bq = (const float*)d_in[2];
    const float* Wk = (const float*)d_in[3];
    const float* bk = (const float*)d_in[4];
    const float* Wv = (const float*)d_in[5];
    const float* bv = (const float*)d_in[6];
    float* out = (float*)d_out;

    cudaFuncSetAttribute(combo_kernel, cudaFuncAttributeMaxDynamicSharedMemorySize, CMB_SMEM);

    // Uneven pipeline {4,8,8,8,4}: small head/tail groups minimize the
    // un-overlapped prologue (proj-only) and epilogue (attn-only) exposure.
    const int NG = 5;
    const int gstart[NG] = {0, 4, 12, 20, 28};
    const int gsize [NG] = {4, 8, 8,  8,  4};

    for (int L = 0; L <= NG; L++) {
        int n_proj = (L < NG) ? gsize[L] * 128 : 0;
        int n_attn = (L > 0) ? gsize[L - 1] * 64 : 0;
        int pb0    = (L < NG) ? gstart[L] : 0;
        int abc0   = (L > 0) ? gstart[L - 1] * 64 : 0;
        combo_kernel<<<n_proj + n_attn, 256, CMB_SMEM>>>(
            x, Wq, bq, Wk, bk, Wv, bv, out, pb0, abc0, n_attn);
    }
}

// round 17
// speedup vs baseline: 1.2174x; 1.0159x over previous
#include <cuda_runtime.h>
#include <cuda_fp16.h>
#include <cstdint>

#define B_ 32
#define C_ 64
#define H_ 128
#define W_ 128
#define HW_ (H_*W_)
#define NTOT_ (B_*C_*HW_)

// fp16 scratch: q/k/v projections + fp16 copy of x for the residual read
__device__ __half g_q[NTOT_];
__device__ __half g_k[NTOT_];
__device__ __half g_v[NTOT_];
__device__ __half g_xh[NTOT_];

// ---------------- helpers ----------------
__device__ __forceinline__ uint32_t smem_u32(const void* p) {
    uint32_t a;
    asm("{ .reg .u64 t; cvta.to.shared.u64 t, %1; cvt.u32.u64 %0, t; }" : "=r"(a) : "l"(p));
    return a;
}
__device__ __forceinline__ uint32_t packh2(float lo, float hi) {
    __half2 h = __floats2half2_rn(lo, hi);
    return *reinterpret_cast<uint32_t*>(&h);
}
__device__ __forceinline__ void ldmx4(uint32_t* r, uint32_t addr) {
    asm volatile("ldmatrix.sync.aligned.m8n8.x4.shared.b16 {%0,%1,%2,%3}, [%4];"
        : "=r"(r[0]), "=r"(r[1]), "=r"(r[2]), "=r"(r[3]) : "r"(addr));
}
__device__ __forceinline__ void ldmx4t(uint32_t* r, uint32_t addr) {
    asm volatile("ldmatrix.sync.aligned.m8n8.x4.trans.shared.b16 {%0,%1,%2,%3}, [%4];"
        : "=r"(r[0]), "=r"(r[1]), "=r"(r[2]), "=r"(r[3]) : "r"(addr));
}
__device__ __forceinline__ void mma_f16(float* d, const uint32_t* a, const uint32_t* b) {
    asm volatile("mma.sync.aligned.m16n8k16.row.col.f32.f16.f16.f32 "
        "{%0,%1,%2,%3}, {%4,%5,%6,%7}, {%8,%9}, {%0,%1,%2,%3};"
        : "+f"(d[0]), "+f"(d[1]), "+f"(d[2]), "+f"(d[3])
        : "r"(a[0]), "r"(a[1]), "r"(a[2]), "r"(a[3]), "r"(b[0]), "r"(b[1]));
}
#define CP16(dst, src) asm volatile("cp.async.cg.shared.global [%0], [%1], 16;" :: "r"(dst), "l"(src) : "memory")
#define CP_COMMIT()    asm volatile("cp.async.commit_group;" ::: "memory")
#define CP_WAIT(n)     asm volatile("cp.async.wait_group %0;" :: "n"(n) : "memory")
// Drop a dirty L2 line WITHOUT write-back (scratch is dead once it's in smem/regs)
#define L2_DISCARD(p)  asm volatile("discard.global.L2 [%0], 128;" :: "l"(p) : "memory")

#define PXT 256          // proj pixel tile (was 128): halves W-fill overhead
#define XPH 264          // 528B rows; 528 mod 128 = 16 -> conflict-free ldmatrix
#define WPH 72
#define PH  136
#define PROJ_SMEM (64*XPH*2 + 3*64*WPH*2)   // 61440 B
#define ATTN_SMEM (2 * 128 * PH * 2)        // 69632 B
#define CMB_SMEM  (ATTN_SMEM > PROJ_SMEM ? ATTN_SMEM : PROJ_SMEM)

// ---------------------------------------------------------------------------
// proj body: q/k/v = W @ x + b (fp16 HMMA), q pre-scaled; also stores fp16 x.
// 256-px tile: warp = 16 out-ch x 128 px (acc[16][4]).
// ---------------------------------------------------------------------------
__device__ __forceinline__ void proj_body(
    const float* __restrict__ x,
    const float* __restrict__ Wq, const float* __restrict__ bq,
    const float* __restrict__ Wk, const float* __restrict__ bk,
    const float* __restrict__ Wv, const float* __restrict__ bv,
    int b, int px0, __half* smp)
{
    __half* Xs = smp;
    __half* Ws = smp + 64 * XPH;
    const uint32_t smb = smem_u32(smp);
    const uint32_t XsB = smb, WsB = smb + 64 * XPH * 2;

    const int tid  = threadIdx.x;
    const int w    = tid >> 5;
    const int lane = tid & 31;
    const int g    = lane >> 2;
    const int tg   = lane & 3;
    const int m0   = (w & 3) * 16;
    const int n0   = (w >> 2) * 128;

    // Fill X tile (fp32 -> fp16) and write the fp16 x sidecar for attn
    const float* xb = x + (size_t)b * C_ * HW_ + px0;
    __half* xhb = g_xh + (size_t)b * C_ * HW_ + px0;
    #pragma unroll 4
    for (int e = tid; e < 64 * (PXT / 4); e += 256) {   // 4096 float4
        int r = e >> 6, c4 = e & 63;
        float4 v = *((const float4*)(xb + r * HW_) + c4);
        uint2 hv = make_uint2(packh2(v.x, v.y), packh2(v.z, v.w));
        *(uint2*)(Xs + r * XPH + c4 * 4) = hv;
        *(uint2*)(xhb + r * HW_ + c4 * 4) = hv;
    }
    #pragma unroll 4
    for (int e = tid; e < 3 * 2048; e += 256) {
        int mtx = e >> 11, i = e & 2047;
        int o = i >> 5, c2 = i & 31;
        const float* Wm = (mtx == 0) ? Wq : (mtx == 1) ? Wk : Wv;
        float2 wv = *((const float2*)(Wm + o * 64) + c2);
        *(uint32_t*)(Ws + mtx * 64 * WPH + o * WPH + c2 * 2) = packh2(wv.x, wv.y);
    }
    __syncthreads();

    const int rsel = lane & 15;
    const int csel = (lane & 16) >> 1;

    #pragma unroll
    for (int mtx = 0; mtx < 3; mtx++) {
        const uint32_t WtB = WsB + (uint32_t)mtx * 64 * WPH * 2;
        float acc[16][4];
        #pragma unroll
        for (int nt = 0; nt < 16; nt++)
            #pragma unroll
            for (int j = 0; j < 4; j++) acc[nt][j] = 0.f;

        #pragma unroll
        for (int k0 = 0; k0 < 64; k0 += 16) {
            uint32_t a[4];
            ldmx4(a, WtB + (uint32_t)((m0 + rsel) * WPH + k0 + csel) * 2);
            #pragma unroll
            for (int ntp = 0; ntp < 8; ntp++) {
                uint32_t bb[4];
                ldmx4t(bb, XsB + (uint32_t)((k0 + rsel) * XPH + n0 + ntp * 16 + csel) * 2);
                mma_f16(acc[2 * ntp],     a, bb);
                mma_f16(acc[2 * ntp + 1], a, bb + 2);
            }
        }

        const float* bm = (mtx == 0) ? bq : (mtx == 1) ? bk : bv;
        __half* gout = ((mtx == 0) ? g_q : (mtx == 1) ? g_k : g_v);
        const float sc = (mtx == 0) ? 0.0078125f : 1.0f;   // 1/sqrt(HW) into q
        float bias0 = bm[m0 + g], bias1 = bm[m0 + g + 8];
        __half* orow0 = gout + ((size_t)b * C_ + m0 + g) * HW_ + px0;
        __half* orow1 = orow0 + 8 * HW_;
        #pragma unroll
        for (int nt = 0; nt < 16; nt++) {
            int col = n0 + nt * 8 + 2 * tg;
            *(uint32_t*)(orow0 + col) =
                packh2((acc[nt][0] + bias0) * sc, (acc[nt][1] + bias0) * sc);
            *(uint32_t*)(orow1 + col) =
                packh2((acc[nt][2] + bias1) * sc, (acc[nt][3] + bias1) * sc);
        }
    }
}

// ---------------------------------------------------------------------------
// attn body: per-(b,c) slice, fp16 HMMA, register P, fp16 residual sidecar.
// ---------------------------------------------------------------------------
#define LOADQ(dst, k0) do { \
    dst[0] = *(const uint32_t*)(qg + (m0 + g) * 128 + (k0) + 2 * tg); \
    dst[1] = *(const uint32_t*)(qg + (m0 + g + 8) * 128 + (k0) + 2 * tg); \
    dst[2] = *(const uint32_t*)(qg + (m0 + g) * 128 + (k0) + 8 + 2 * tg); \
    dst[3] = *(const uint32_t*)(qg + (m0 + g + 8) * 128 + (k0) + 8 + 2 * tg); \
} while (0)

__device__ __forceinline__ void attn_body(
    float* __restrict__ out, int bc, __half* sma)
{
    const uint32_t smb = smem_u32(sma);
    const uint32_t KsB = smb, VsB = smb + 128 * PH * 2;

    const size_t base = (size_t)bc * HW_;
    const int tid  = threadIdx.x;
    const int wid  = tid >> 5;
    const int lane = tid & 31;
    const int g    = lane >> 2;
    const int tg   = lane & 3;
    const int m0   = wid * 16;
    const int rsel = lane & 15;
    const int csel = (lane & 16) >> 1;

    // Async fills: K -> group0, V -> group1
    const uint4* kg = (const uint4*)(g_k + base);
    const uint4* vg = (const uint4*)(g_v + base);
    #pragma unroll
    for (int e = tid; e < 2048; e += 256) {
        uint32_t off = (uint32_t)((e >> 4) * PH + (e & 15) * 8) * 2;
        CP16(KsB + off, kg + e);
    }
    CP_COMMIT();
    #pragma unroll
    for (int e = tid; e < 2048; e += 256) {
        uint32_t off = (uint32_t)((e >> 4) * PH + (e & 15) * 8) * 2;
        CP16(VsB + off, vg + e);
    }
    CP_COMMIT();

    // Q: double-buffered A-fragments from gmem/L2 (2 stages in flight)
    const __half* qg = g_q + base;
    uint32_t aqc[4], aqn[4];
    LOADQ(aqc, 0);       // stage 0 in flight while K lands

    CP_WAIT(1);          // K landed (in smem)
    __syncthreads();
    // K gmem lines are dead now — drop them from L2 without write-back
    L2_DISCARD((const char*)(g_k + base) + tid * 128);

    // ---- MM1: S = Q.K^T (q pre-scaled) ----
    float acc[16][4];
    #pragma unroll
    for (int nt = 0; nt < 16; nt++)
        #pragma unroll
        for (int j = 0; j < 4; j++) acc[nt][j] = 0.f;

    #pragma unroll
    for (int ks = 0; ks < 8; ks++) {
        const int k0 = ks * 16;
        if (ks < 7) LOADQ(aqn, k0 + 16);   // prefetch next stage under mmas
        #pragma unroll
        for (int ntp = 0; ntp < 8; ntp++) {
            uint32_t kb[4];
            ldmx4(kb, KsB + (uint32_t)((ntp * 16 + csel + (lane & 7)) * PH + k0 + (lane & 8)) * 2);
            mma_f16(acc[2 * ntp],     aqc, kb);
            mma_f16(acc[2 * ntp + 1], aqc, kb + 2);
        }
        #pragma unroll
        for (int j = 0; j < 4; j++) aqc[j] = aqn[j];
    }

    // ---- softmax; P packed to fp16 in regs ----
    float sum0 = 0.f, sum1 = 0.f;
    uint32_t ph[16][2];
    #pragma unroll
    for (int nt = 0; nt < 16; nt++) {
        float e0 = __expf(acc[nt][0]);
        float e1 = __expf(acc[nt][1]);
        float e2 = __expf(acc[nt][2]);
        float e3 = __expf(acc[nt][3]);
        sum0 += e0 + e1;  sum1 += e2 + e3;
        ph[nt][0] = packh2(e0, e1);
        ph[nt][1] = packh2(e2, e3);
    }
    sum0 += __shfl_xor_sync(0xffffffffu, sum0, 1);
    sum0 += __shfl_xor_sync(0xffffffffu, sum0, 2);
    sum1 += __shfl_xor_sync(0xffffffffu, sum1, 1);
    sum1 += __shfl_xor_sync(0xffffffffu, sum1, 2);
    const float rin0 = 1.0f / sum0, rin1 = 1.0f / sum1;

    CP_WAIT(0);          // V landed (in smem)
    __syncthreads();
    // Q fully consumed by all warps (barrier above); V gmem lines dead too
    L2_DISCARD((const char*)(g_q + base) + tid * 128);
    L2_DISCARD((const char*)(g_v + base) + tid * 128);

    // ---- MM2: O = P.V + x (fp16 sidecar residual) ----
    const __half* xh = g_xh + base;
    float* og = out + base;
    #pragma unroll
    for (int hf = 0; hf < 2; hf++) {
        const int w00 = hf * 64;

        // Prefetch fp16 residuals for this half (hidden under mma chain)
        __half2 xv[16];
        #pragma unroll
        for (int wt = 0; wt < 8; wt++) {
            int col = w00 + wt * 8 + 2 * tg;
            xv[2 * wt]     = *(const __half2*)(xh + (m0 + g) * W_ + col);
            xv[2 * wt + 1] = *(const __half2*)(xh + (m0 + g + 8) * W_ + col);
        }

        float o[8][4];
        #pragma unroll
        for (int wt = 0; wt < 8; wt++)
            #pragma unroll
            for (int j = 0; j < 4; j++) o[wt][j] = 0.f;

        #pragma unroll
        for (int s = 0; s < 8; s++) {
            const int k0 = s * 16;
            uint32_t a[4] = { ph[2*s][0], ph[2*s][1], ph[2*s+1][0], ph[2*s+1][1] };
            #pragma unroll
            for (int wtp = 0; wtp < 4; wtp++) {
                uint32_t vb[4];
                ldmx4t(vb, VsB + (uint32_t)((k0 + rsel) * PH + w00 + wtp * 16 + csel) * 2);
                mma_f16(o[2 * wtp],     a, vb);
                mma_f16(o[2 * wtp + 1], a, vb + 2);
            }
        }

        #pragma unroll
        for (int wt = 0; wt < 8; wt++) {
            int col = w00 + wt * 8 + 2 * tg;
            float2 f0 = __half22float2(xv[2 * wt]);
            float2 f1 = __half22float2(xv[2 * wt + 1]);
            *(float2*)(og + (m0 + g) * W_ + col) =
                make_float2(o[wt][0] * rin0 + f0.x, o[wt][1] * rin0 + f0.y);
            *(float2*)(og + (m0 + g + 8) * W_ + col) =
                make_float2(o[wt][2] * rin1 + f1.x, o[wt][3] * rin1 + f1.y);
        }
    }

    // xh fully consumed by all warps after this barrier
    __syncthreads();
    L2_DISCARD((const char*)(g_xh + base) + tid * 128);
}

// ---------------------------------------------------------------------------
// Combo kernel: first n_attn CTAs run attn(prev group), rest run proj(cur).
// ---------------------------------------------------------------------------
__global__ __launch_bounds__(256, 2) void combo_kernel(
    const float* __restrict__ x,
    const float* __restrict__ Wq, const float* __restrict__ bq,
    const float* __restrict__ Wk, const float* __restrict__ bk,
    const float* __restrict__ Wv, const float* __restrict__ bv,
    float* __restrict__ out,
    int proj_b0, int attn_bc0, int n_attn)
{
    extern __shared__ __half smc[];
    const int bi = (int)blockIdx.x;
    if (bi < n_attn) {
        attn_body(out, attn_bc0 + bi, smc);
    } else {
        const int pb = bi - n_attn;                    // 64 proj CTAs per batch
        proj_body(x, Wq, bq, Wk, bk, Wv, bv,
                  proj_b0 + (pb >> 6), (pb & 63) * PXT, smc);
    }
}

// ---------------------------------------------------------------------------
extern "C" void kernel_launch(void* const* d_in, const int* in_sizes, int n_in,
                              void* d_out, int out_size)
{
    const float* x  = (const float*)d_in[0];
    const float* Wq = (const float*)d_in[1];
    const float* bq = (const float*)d_in[2];
    const float* Wk = (const float*)d_in[3];
    const float* bk = (const float*)d_in[4];
    const float* Wv = (const float*)d_in[5];
    const float* bv = (const float*)d_in[6];
    float* out = (float*)d_out;

    cudaFuncSetAttribute(combo_kernel, cudaFuncAttributeMaxDynamicSharedMemorySize, CMB_SMEM);

    // Uneven pipeline {4,8,8,8,4}; proj CTAs = 64 per batch (256-px tiles).
    const int NG = 5;
    const int gstart[NG] = {0, 4, 12, 20, 28};
    const int gsize [NG] = {4, 8, 8,  8,  4};

    for (int L = 0; L <= NG; L++) {
        int n_proj = (L < NG) ? gsize[L] * (HW_ / PXT) : 0;
        int n_attn = (L > 0) ? gsize[L - 1] * 64 : 0;
        int pb0    = (L < NG) ? gstart[L] : 0;
        int abc0   = (L > 0) ? gstart[L - 1] * 64 : 0;
        combo_kernel<<<n_proj + n_attn, 256, CMB_SMEM>>>(
            x, Wq, bq, Wk, bk, Wv, bv, out, pb0, abc0, n_attn);
    }
}